// round 13
// baseline (speedup 1.0000x reference)
#include <cuda_runtime.h>
#include <cuda_bf16.h>
#include <math.h>
#include <stdint.h>

#define D 128
#define MAX_N 50000
#define MAX_E 600000
#define NPAD 50048

// ---------------- scratch (static device allocations; no runtime alloc) ---------
__device__ int   g_deg[3][NPAD];
__device__ int   g_ofs[3][NPAD + 1];
__device__ int   g_cur[3][NPAD];
__device__ int   g_esrc[3 * MAX_E];
// bf16 hi/lo split A-source tables: [n][128]
__device__ __nv_bfloat16 g_hi_rates[MAX_N * D], g_lo_rates[MAX_N * D];
__device__ __nv_bfloat16 g_hi_rev[MAX_N * D],   g_lo_rev[MAX_N * D];
__device__ __nv_bfloat16 g_hi_fol[MAX_N * D],   g_lo_fol[MAX_N * D];
__device__ __nv_bfloat16 g_hi_xu[MAX_N * D],    g_lo_xu[MAX_N * D];
__device__ __nv_bfloat16 g_hi_xi[MAX_N * D],    g_lo_xi[MAX_N * D];
// transposed combined weights, bf16 hi/lo split: [j][k]
__device__ __nv_bfloat16 g_wbt_user_hi[128 * 384];
__device__ __nv_bfloat16 g_wbt_user_lo[128 * 384];
__device__ __nv_bfloat16 g_wbt_item_hi[128 * 256];
__device__ __nv_bfloat16 g_wbt_item_lo[128 * 256];
__device__ float g_bias_user[D];
__device__ float g_bias_item[D];

// ---------------- helpers ---------------------------------------------------------
__device__ __forceinline__ uint32_t smem_u32(const void* p) {
    uint32_t a;
    asm("{ .reg .u64 t; cvta.to.shared.u64 t, %1; cvt.u32.u64 %0, t; }"
        : "=r"(a) : "l"(p));
    return a;
}
__device__ __forceinline__ void f2_to_hilo(float f0, float f1, uint32_t& hi, uint32_t& lo) {
    __nv_bfloat16 h0 = __float2bfloat16_rn(f0);
    __nv_bfloat16 h1 = __float2bfloat16_rn(f1);
    __nv_bfloat16 l0 = __float2bfloat16_rn(f0 - __bfloat162float(h0));
    __nv_bfloat16 l1 = __float2bfloat16_rn(f1 - __bfloat162float(h1));
    __nv_bfloat162 hp = __halves2bfloat162(h0, h1);
    __nv_bfloat162 lp = __halves2bfloat162(l0, l1);
    hi = *(uint32_t*)&hp;
    lo = *(uint32_t*)&lp;
}

#define LDM_X4(r0, r1, r2, r3, addr)                                              \
    asm volatile("ldmatrix.sync.aligned.m8n8.x4.shared.b16 {%0,%1,%2,%3}, [%4];"  \
                 : "=r"(r0), "=r"(r1), "=r"(r2), "=r"(r3) : "r"(addr))

#define MMA16816(c, a, b0, b1)                                                    \
    asm volatile("mma.sync.aligned.m16n8k16.row.col.f32.bf16.bf16.f32 "           \
                 "{%0,%1,%2,%3}, {%4,%5,%6,%7}, {%8,%9}, {%0,%1,%2,%3};"          \
                 : "+f"((c)[0]), "+f"((c)[1]), "+f"((c)[2]), "+f"((c)[3])         \
                 : "r"((a)[0]), "r"((a)[1]), "r"((a)[2]), "r"((a)[3]),            \
                   "r"(b0), "r"(b1))

#define CPA16(dst, src, sz)                                                       \
    asm volatile("cp.async.ca.shared.global [%0], [%1], 16, %2;"                  \
                 :: "r"(dst), "l"(src), "r"(sz) : "memory")
#define CPA_COMMIT() asm volatile("cp.async.commit_group;" ::: "memory")
#define CPA_WAIT(N)  asm volatile("cp.async.wait_group %0;" :: "n"(N) : "memory")

// ---------------- zero degree counters -------------------------------------------
__global__ void zero_deg() {
    int i = blockIdx.x * blockDim.x + threadIdx.x;
    if (i < NPAD) { g_deg[0][i] = 0; g_deg[1][i] = 0; g_deg[2][i] = 0; }
}

// ---------------- degree histogram ------------------------------------------------
__global__ void hist_kernel(const int* __restrict__ ei0, const int* __restrict__ ei1,
                            const int* __restrict__ ei2, int E) {
    int rel = blockIdx.y;
    const int* ei = (rel == 0) ? ei0 : (rel == 1) ? ei1 : ei2;
    int e = blockIdx.x * blockDim.x + threadIdx.x;
    if (e < E) atomicAdd(&g_deg[rel][ei[E + e]], 1);
}

// ---------------- exclusive scan (one block per relation) ------------------------
__global__ void scan_kernel(int n0, int n1, int n2) {
    int rel = blockIdx.x;
    int n = (rel == 0) ? n0 : (rel == 1) ? n1 : n2;
    __shared__ int shw[32];
    int t = threadIdx.x;
    int lane = t & 31;
    int wid = t >> 5;
    int running = 0;
    for (int base = 0; base < n; base += 1024) {
        int idx = base + t;
        int v = (idx < n) ? g_deg[rel][idx] : 0;
        int x = v;
#pragma unroll
        for (int off = 1; off < 32; off <<= 1) {
            int y = __shfl_up_sync(0xffffffffu, x, off);
            if (lane >= off) x += y;
        }
        if (lane == 31) shw[wid] = x;
        __syncthreads();
        if (wid == 0) {
            int s = shw[lane];
#pragma unroll
            for (int off = 1; off < 32; off <<= 1) {
                int y = __shfl_up_sync(0xffffffffu, s, off);
                if (lane >= off) s += y;
            }
            shw[lane] = s;
        }
        __syncthreads();
        int warpbase = (wid > 0) ? shw[wid - 1] : 0;
        int excl = running + warpbase + x - v;
        if (idx < n) {
            g_ofs[rel][idx] = excl;
            g_cur[rel][idx] = excl;
        }
        int total = shw[31];
        __syncthreads();
        running += total;
    }
    if (t == 0) g_ofs[rel][n] = running;
}

// ---------------- permute src ids into CSR order ---------------------------------
__global__ void permute_kernel(const int* __restrict__ ei0, const int* __restrict__ ei1,
                               const int* __restrict__ ei2, int E) {
    int rel = blockIdx.y;
    const int* ei = (rel == 0) ? ei0 : (rel == 1) ? ei1 : ei2;
    int e = blockIdx.x * blockDim.x + threadIdx.x;
    if (e < E) {
        int src = __ldg(ei + e);
        int dst = __ldg(ei + E + e);
        int pos = atomicAdd(&g_cur[rel][dst], 1);
        g_esrc[rel * MAX_E + pos] = src;
    }
}

// ---------------- x feature pre-split to bf16 hi/lo ------------------------------
__global__ void convert_x(const float* __restrict__ x_user, const float* __restrict__ x_item,
                          int n_user, int n_item) {
    int which = blockIdx.y;
    const float* x = which ? x_item : x_user;
    __nv_bfloat16* hi = which ? g_hi_xi : g_hi_xu;
    __nv_bfloat16* lo = which ? g_lo_xi : g_lo_xu;
    int n4 = (which ? n_item : n_user) * 32;   // float4 count
    int t = blockIdx.x * blockDim.x + threadIdx.x;
    if (t < n4) {
        float4 v = ((const float4*)x)[t];
        uint32_t h0, l0, h1, l1;
        f2_to_hilo(v.x, v.y, h0, l0);
        f2_to_hilo(v.z, v.w, h1, l1);
        *(uint2*)(hi + (size_t)t * 4) = make_uint2(h0, h1);
        *(uint2*)(lo + (size_t)t * 4) = make_uint2(l0, l1);
    }
}

// ---------------- atomic-free aggregation: mean -> bf16 hi/lo --------------------
__global__ void aggregate_kernel(const float* __restrict__ x_user,
                                 const float* __restrict__ x_item,
                                 int n_user, int n_item) {
    int rel = blockIdx.y;
    int n = (rel == 0) ? n_item : n_user;
    const float* x = (rel == 1) ? x_item : x_user;
    __nv_bfloat16* mhi = (rel == 0) ? g_hi_rates : (rel == 1) ? g_hi_rev : g_hi_fol;
    __nv_bfloat16* mlo = (rel == 0) ? g_lo_rates : (rel == 1) ? g_lo_rev : g_lo_fol;

    int w = (blockIdx.x * blockDim.x + threadIdx.x) >> 5;
    int lane = threadIdx.x & 31;
    if (w >= n) return;

    int start = g_ofs[rel][w];
    int end   = g_ofs[rel][w + 1];
    const int* esrc = g_esrc + rel * MAX_E;
    const size_t loff = (size_t)(lane * 4);

    float4 a0 = make_float4(0.f, 0.f, 0.f, 0.f);
    float4 a1 = make_float4(0.f, 0.f, 0.f, 0.f);
    float4 a2 = make_float4(0.f, 0.f, 0.f, 0.f);
    float4 a3 = make_float4(0.f, 0.f, 0.f, 0.f);
    int e = start;
    for (; e + 4 <= end; e += 4) {
        int s0 = __ldg(esrc + e);
        int s1 = __ldg(esrc + e + 1);
        int s2 = __ldg(esrc + e + 2);
        int s3 = __ldg(esrc + e + 3);
        float4 v0 = *(const float4*)(x + (size_t)s0 * D + loff);
        float4 v1 = *(const float4*)(x + (size_t)s1 * D + loff);
        float4 v2 = *(const float4*)(x + (size_t)s2 * D + loff);
        float4 v3 = *(const float4*)(x + (size_t)s3 * D + loff);
        a0.x += v0.x; a0.y += v0.y; a0.z += v0.z; a0.w += v0.w;
        a1.x += v1.x; a1.y += v1.y; a1.z += v1.z; a1.w += v1.w;
        a2.x += v2.x; a2.y += v2.y; a2.z += v2.z; a2.w += v2.w;
        a3.x += v3.x; a3.y += v3.y; a3.z += v3.z; a3.w += v3.w;
    }
    for (; e < end; e++) {
        int s0 = __ldg(esrc + e);
        float4 v0 = *(const float4*)(x + (size_t)s0 * D + loff);
        a0.x += v0.x; a0.y += v0.y; a0.z += v0.z; a0.w += v0.w;
    }
    int deg = end - start;
    float sc = (deg > 0) ? (1.0f / (float)deg) : 0.0f;
    float4 r;
    r.x = (a0.x + a1.x + a2.x + a3.x) * sc;
    r.y = (a0.y + a1.y + a2.y + a3.y) * sc;
    r.z = (a0.z + a1.z + a2.z + a3.z) * sc;
    r.w = (a0.w + a1.w + a2.w + a3.w) * sc;
    uint32_t h0, l0, h1, l1;
    f2_to_hilo(r.x, r.y, h0, l0);
    f2_to_hilo(r.z, r.w, h1, l1);
    *(uint2*)(mhi + (size_t)w * D + loff) = make_uint2(h0, h1);
    *(uint2*)(mlo + (size_t)w * D + loff) = make_uint2(l0, l1);
}

// ---------------- combined-weight prep: transposed bf16 hi/lo --------------------
__global__ void build_user_wc(const float* __restrict__ Wl_rev, const float* __restrict__ bl_rev,
                              const float* __restrict__ Wr_rev,
                              const float* __restrict__ Wl_fol, const float* __restrict__ bl_fol,
                              const float* __restrict__ Wr_fol) {
    int t = blockIdx.x * blockDim.x + threadIdx.x;
    if (t < 384 * 128) {
        int k = t >> 7, j = t & 127;
        float v;
        if (k < 128)       v = 0.5f * Wl_rev[j * D + k];
        else if (k < 256)  v = 0.5f * Wl_fol[j * D + (k - 128)];
        else               v = 0.5f * (Wr_rev[j * D + (k - 256)] + Wr_fol[j * D + (k - 256)]);
        __nv_bfloat16 hi = __float2bfloat16_rn(v);
        __nv_bfloat16 lo = __float2bfloat16_rn(v - __bfloat162float(hi));
        g_wbt_user_hi[j * 384 + k] = hi;
        g_wbt_user_lo[j * 384 + k] = lo;
    }
    if (t < D) g_bias_user[t] = 0.5f * (bl_rev[t] + bl_fol[t]);
}

__global__ void build_item_wc(const float* __restrict__ Wl, const float* __restrict__ bl,
                              const float* __restrict__ Wr) {
    int t = blockIdx.x * blockDim.x + threadIdx.x;
    if (t < 256 * 128) {
        int k = t >> 7, j = t & 127;
        float v = (k < 128) ? Wl[j * D + k] : Wr[j * D + (k - 128)];
        __nv_bfloat16 hi = __float2bfloat16_rn(v);
        __nv_bfloat16 lo = __float2bfloat16_rn(v - __bfloat162float(hi));
        g_wbt_item_hi[j * 256 + k] = hi;
        g_wbt_item_lo[j * 256 + k] = lo;
    }
    if (t < D) g_bias_item[t] = bl[t];
}

// ---------------- mma.sync bf16x3 GEMM, cp.async double-buffered -----------------
// 128x128 output tile per CTA, 256 thr = 8 warps (4 row-groups x 2 col-groups).
// K in chunks of 64; A/B bf16 hi/lo pre-split in global, staged via cp.async.
#define LDB 144
#define SA_HI 0
#define SA_LO 18432
#define SB_HI 36864
#define SB_LO 55296
#define STAGE 73728
#define SM_BIAS_OFF (2 * STAGE)
#define SM_TOT (2 * STAGE + 512)

__global__ __launch_bounds__(256, 1)
void gemm_mma(float* __restrict__ out_user, float* __restrict__ out_item,
              int n_user, int n_item) {
    extern __shared__ char smem[];
    uint32_t sb = smem_u32(smem);
    const int tid = threadIdx.x;
    const int lane = tid & 31;
    const int w = tid >> 5;
    const int wr = w & 3;          // row group: 32 rows
    const int wc = w >> 2;         // col group: 64 cols
    const int mode = blockIdx.y;   // 0 user, 1 item
    const int nrows = mode ? n_item : n_user;
    const int nch = mode ? 4 : 6;
    const int KS = mode ? 256 : 384;
    const __nv_bfloat16* wbh = mode ? g_wbt_item_hi : g_wbt_user_hi;
    const __nv_bfloat16* wbl = mode ? g_wbt_item_lo : g_wbt_user_lo;
    const float* bias = mode ? g_bias_item : g_bias_user;
    float* out = mode ? out_item : out_user;
    const int row0 = blockIdx.x * 128;
    if (row0 >= nrows) return;

    if (tid < 128) ((float*)(smem + SM_BIAS_OFF))[tid] = bias[tid];

    const int r_st = tid >> 1;     // staging row 0..127
    const int half = tid & 1;      // 32-element half
    const int gra = min(row0 + r_st, nrows - 1);      // clamped source row
    const uint32_t asz = (row0 + r_st < nrows) ? 16u : 0u;  // zero-fill OOB rows

    // stage chunk c into buffer (c & 1): 16 x 16B cp.async per thread
    auto stage = [&](int c) {
        const __nv_bfloat16 *ahi, *alo;
        if (mode == 0) {
            if (c < 2)      { ahi = g_hi_rev;   alo = g_lo_rev; }
            else if (c < 4) { ahi = g_hi_fol;   alo = g_lo_fol; }
            else            { ahi = g_hi_xu;    alo = g_lo_xu; }
        } else {
            if (c < 2)      { ahi = g_hi_rates; alo = g_lo_rates; }
            else            { ahi = g_hi_xi;    alo = g_lo_xi; }
        }
        uint32_t bb = sb + (uint32_t)((c & 1) * STAGE);
        uint32_t doff = (uint32_t)(r_st * LDB + half * 64);
        const __nv_bfloat16* sa_h = ahi + (size_t)gra * D + (c & 1) * 64 + half * 32;
        const __nv_bfloat16* sa_l = alo + (size_t)gra * D + (c & 1) * 64 + half * 32;
        const __nv_bfloat16* sb_h = wbh + (size_t)r_st * KS + c * 64 + half * 32;
        const __nv_bfloat16* sb_l = wbl + (size_t)r_st * KS + c * 64 + half * 32;
#pragma unroll
        for (int q = 0; q < 4; q++) {
            CPA16(bb + SA_HI + doff + q * 16, sa_h + q * 8, asz);
            CPA16(bb + SA_LO + doff + q * 16, sa_l + q * 8, asz);
            CPA16(bb + SB_HI + doff + q * 16, sb_h + q * 8, 16u);
            CPA16(bb + SB_LO + doff + q * 16, sb_l + q * 8, 16u);
        }
        CPA_COMMIT();
    };

    float acc[2][8][4];
#pragma unroll
    for (int i = 0; i < 2; i++)
#pragma unroll
        for (int j = 0; j < 8; j++)
#pragma unroll
            for (int q = 0; q < 4; q++) acc[i][j][q] = 0.f;

    stage(0);

    for (int c = 0; c < nch; c++) {
        __syncthreads();               // all warps done reading buffer (c+1)&1
        if (c + 1 < nch) {
            stage(c + 1);
            CPA_WAIT(1);               // chunk c's group complete
        } else {
            CPA_WAIT(0);
        }
        __syncthreads();               // staged data visible to all warps

        uint32_t bufb = sb + (uint32_t)((c & 1) * STAGE);
#pragma unroll
        for (int ks = 0; ks < 4; ks++) {
            uint32_t cb = (uint32_t)(ks * 32 + (lane >> 4) * 16);
            uint32_t ar = (uint32_t)((wr * 32 + (lane & 15)) * LDB);
            uint32_t ah[2][4], al[2][4];
            LDM_X4(ah[0][0], ah[0][1], ah[0][2], ah[0][3], bufb + SA_HI + ar + cb);
            LDM_X4(ah[1][0], ah[1][1], ah[1][2], ah[1][3], bufb + SA_HI + ar + 16 * LDB + cb);
            LDM_X4(al[0][0], al[0][1], al[0][2], al[0][3], bufb + SA_LO + ar + cb);
            LDM_X4(al[1][0], al[1][1], al[1][2], al[1][3], bufb + SA_LO + ar + 16 * LDB + cb);
#pragma unroll
            for (int ng = 0; ng < 4; ng++) {
                uint32_t br = (uint32_t)((wc * 64 + ng * 16 + (lane & 15)) * LDB);
                uint32_t bh0, bh1, bh2, bh3, bl0, bl1, bl2, bl3;
                LDM_X4(bh0, bh1, bh2, bh3, bufb + SB_HI + br + cb);
                LDM_X4(bl0, bl1, bl2, bl3, bufb + SB_LO + br + cb);
#pragma unroll
                for (int mt = 0; mt < 2; mt++) {
                    MMA16816(acc[mt][2 * ng],     ah[mt], bh0, bh2);
                    MMA16816(acc[mt][2 * ng],     al[mt], bh0, bh2);
                    MMA16816(acc[mt][2 * ng],     ah[mt], bl0, bl2);
                    MMA16816(acc[mt][2 * ng + 1], ah[mt], bh1, bh3);
                    MMA16816(acc[mt][2 * ng + 1], al[mt], bh1, bh3);
                    MMA16816(acc[mt][2 * ng + 1], ah[mt], bl1, bl3);
                }
            }
        }
    }

    // ---- epilogue: acc + bias -> out ----
    const float* bs = (const float*)(smem + SM_BIAS_OFF);
#pragma unroll
    for (int mt = 0; mt < 2; mt++) {
        int r0g = row0 + wr * 32 + mt * 16 + (lane >> 2);
        int r1g = r0g + 8;
#pragma unroll
        for (int nt = 0; nt < 8; nt++) {
            int j = wc * 64 + nt * 8 + (lane & 3) * 2;
            float b0 = bs[j], b1 = bs[j + 1];
            if (r0g < nrows) {
                float2 o = make_float2(acc[mt][nt][0] + b0, acc[mt][nt][1] + b1);
                *(float2*)(out + (size_t)r0g * D + j) = o;
            }
            if (r1g < nrows) {
                float2 o = make_float2(acc[mt][nt][2] + b0, acc[mt][nt][3] + b1);
                *(float2*)(out + (size_t)r1g * D + j) = o;
            }
        }
    }
}

// ---------------- launch ---------------------------------------------------------
extern "C" void kernel_launch(void* const* d_in, const int* in_sizes, int n_in,
                              void* d_out, int out_size) {
    const float* x_user   = (const float*)d_in[0];
    const float* x_item   = (const float*)d_in[1];
    const int*   ei_rates = (const int*)d_in[2];
    const int*   ei_rev   = (const int*)d_in[3];
    const int*   ei_fol   = (const int*)d_in[4];
    const float* Wl_rates = (const float*)d_in[5];
    const float* bl_rates = (const float*)d_in[6];
    const float* Wr_rates = (const float*)d_in[7];
    const float* Wl_rev   = (const float*)d_in[8];
    const float* bl_rev   = (const float*)d_in[9];
    const float* Wr_rev   = (const float*)d_in[10];
    const float* Wl_fol   = (const float*)d_in[11];
    const float* bl_fol   = (const float*)d_in[12];
    const float* Wr_fol   = (const float*)d_in[13];

    const int n_user = in_sizes[0] / D;
    const int n_item = in_sizes[1] / D;
    const int E      = in_sizes[2] / 2;

    float* out_user = (float*)d_out;
    float* out_item = out_user + (size_t)n_user * D;

    // opt-in to >48KB dynamic smem (host attribute, not an allocation)
    cudaFuncSetAttribute(gemm_mma, cudaFuncAttributeMaxDynamicSharedMemorySize, SM_TOT);

    // 1) prep: zero counters, split weights + x features to bf16 hi/lo
    zero_deg<<<(NPAD + 255) / 256, 256>>>();
    build_user_wc<<<(384 * 128 + 255) / 256, 256>>>(Wl_rev, bl_rev, Wr_rev,
                                                    Wl_fol, bl_fol, Wr_fol);
    build_item_wc<<<(256 * 128 + 255) / 256, 256>>>(Wl_rates, bl_rates, Wr_rates);
    {
        int max_n = (n_user > n_item) ? n_user : n_item;
        dim3 grid((max_n * 32 + 255) / 256, 2);
        convert_x<<<grid, 256>>>(x_user, x_item, n_user, n_item);
    }

    // 2) CSR build: histogram -> scan -> permute
    {
        dim3 grid((E + 255) / 256, 3);
        hist_kernel<<<grid, 256>>>(ei_rates, ei_rev, ei_fol, E);
        scan_kernel<<<3, 1024>>>(n_item, n_user, n_user);
        permute_kernel<<<grid, 256>>>(ei_rates, ei_rev, ei_fol, E);
    }

    // 3) atomic-free aggregation (mean -> bf16 hi/lo) for all 3 relations
    {
        int max_n = (n_user > n_item) ? n_user : n_item;
        dim3 grid((max_n + 7) / 8, 3);
        aggregate_kernel<<<grid, 256>>>(x_user, x_item, n_user, n_item);
    }

    // 4) pipelined mma.sync bf16x3 GEMM + bias for both node types
    {
        int max_rows = (n_user > n_item) ? n_user : n_item;
        dim3 grid((max_rows + 127) / 128, 2);
        gemm_mma<<<grid, 256, SM_TOT>>>(out_user, out_item, n_user, n_item);
    }
}

// round 14
// speedup vs baseline: 1.0251x; 1.0251x over previous
#include <cuda_runtime.h>
#include <cuda_bf16.h>
#include <math.h>
#include <stdint.h>

#define D 128
#define MAX_N 50000
#define MAX_E 600000
#define NPAD 50048

// ---------------- scratch (static device allocations; no runtime alloc) ---------
__device__ int   g_deg[3][NPAD];
__device__ int   g_ofs[3][NPAD + 1];
__device__ int   g_cur[3][NPAD];
__device__ int   g_esrc[3 * MAX_E];
// bf16 hi/lo split A-source tables: [n][128]
__device__ __nv_bfloat16 g_hi_rates[MAX_N * D], g_lo_rates[MAX_N * D];
__device__ __nv_bfloat16 g_hi_rev[MAX_N * D],   g_lo_rev[MAX_N * D];
__device__ __nv_bfloat16 g_hi_fol[MAX_N * D],   g_lo_fol[MAX_N * D];
__device__ __nv_bfloat16 g_hi_xu[MAX_N * D],    g_lo_xu[MAX_N * D];
__device__ __nv_bfloat16 g_hi_xi[MAX_N * D],    g_lo_xi[MAX_N * D];
// transposed combined weights, bf16 hi/lo split: [j][k]
__device__ __nv_bfloat16 g_wbt_user_hi[128 * 384];
__device__ __nv_bfloat16 g_wbt_user_lo[128 * 384];
__device__ __nv_bfloat16 g_wbt_item_hi[128 * 256];
__device__ __nv_bfloat16 g_wbt_item_lo[128 * 256];
__device__ float g_bias_user[D];
__device__ float g_bias_item[D];

// ---------------- helpers ---------------------------------------------------------
__device__ __forceinline__ uint32_t smem_u32(const void* p) {
    uint32_t a;
    asm("{ .reg .u64 t; cvta.to.shared.u64 t, %1; cvt.u32.u64 %0, t; }"
        : "=r"(a) : "l"(p));
    return a;
}
__device__ __forceinline__ void f2_to_hilo(float f0, float f1, uint32_t& hi, uint32_t& lo) {
    __nv_bfloat16 h0 = __float2bfloat16_rn(f0);
    __nv_bfloat16 h1 = __float2bfloat16_rn(f1);
    __nv_bfloat16 l0 = __float2bfloat16_rn(f0 - __bfloat162float(h0));
    __nv_bfloat16 l1 = __float2bfloat16_rn(f1 - __bfloat162float(h1));
    __nv_bfloat162 hp = __halves2bfloat162(h0, h1);
    __nv_bfloat162 lp = __halves2bfloat162(l0, l1);
    hi = *(uint32_t*)&hp;
    lo = *(uint32_t*)&lp;
}

#define LDM_X4(r0, r1, r2, r3, addr)                                              \
    asm volatile("ldmatrix.sync.aligned.m8n8.x4.shared.b16 {%0,%1,%2,%3}, [%4];"  \
                 : "=r"(r0), "=r"(r1), "=r"(r2), "=r"(r3) : "r"(addr))

#define MMA16816(c, a, b0, b1)                                                    \
    asm volatile("mma.sync.aligned.m16n8k16.row.col.f32.bf16.bf16.f32 "           \
                 "{%0,%1,%2,%3}, {%4,%5,%6,%7}, {%8,%9}, {%0,%1,%2,%3};"          \
                 : "+f"((c)[0]), "+f"((c)[1]), "+f"((c)[2]), "+f"((c)[3])         \
                 : "r"((a)[0]), "r"((a)[1]), "r"((a)[2]), "r"((a)[3]),            \
                   "r"(b0), "r"(b1))

#define CPA16(dst, src, sz)                                                       \
    asm volatile("cp.async.ca.shared.global [%0], [%1], 16, %2;"                  \
                 :: "r"(dst), "l"(src), "r"(sz) : "memory")
#define CPA_COMMIT() asm volatile("cp.async.commit_group;" ::: "memory")
#define CPA_WAIT(N)  asm volatile("cp.async.wait_group %0;" :: "n"(N) : "memory")

// ---------------- zero degree counters -------------------------------------------
__global__ void zero_deg() {
    int i = blockIdx.x * blockDim.x + threadIdx.x;
    if (i < NPAD) { g_deg[0][i] = 0; g_deg[1][i] = 0; g_deg[2][i] = 0; }
}

// ---------------- degree histogram ------------------------------------------------
__global__ void hist_kernel(const int* __restrict__ ei0, const int* __restrict__ ei1,
                            const int* __restrict__ ei2, int E) {
    int rel = blockIdx.y;
    const int* ei = (rel == 0) ? ei0 : (rel == 1) ? ei1 : ei2;
    int e = blockIdx.x * blockDim.x + threadIdx.x;
    if (e < E) atomicAdd(&g_deg[rel][ei[E + e]], 1);
}

// ---------------- exclusive scan (one block per relation) ------------------------
__global__ void scan_kernel(int n0, int n1, int n2) {
    int rel = blockIdx.x;
    int n = (rel == 0) ? n0 : (rel == 1) ? n1 : n2;
    __shared__ int shw[32];
    int t = threadIdx.x;
    int lane = t & 31;
    int wid = t >> 5;
    int running = 0;
    for (int base = 0; base < n; base += 1024) {
        int idx = base + t;
        int v = (idx < n) ? g_deg[rel][idx] : 0;
        int x = v;
#pragma unroll
        for (int off = 1; off < 32; off <<= 1) {
            int y = __shfl_up_sync(0xffffffffu, x, off);
            if (lane >= off) x += y;
        }
        if (lane == 31) shw[wid] = x;
        __syncthreads();
        if (wid == 0) {
            int s = shw[lane];
#pragma unroll
            for (int off = 1; off < 32; off <<= 1) {
                int y = __shfl_up_sync(0xffffffffu, s, off);
                if (lane >= off) s += y;
            }
            shw[lane] = s;
        }
        __syncthreads();
        int warpbase = (wid > 0) ? shw[wid - 1] : 0;
        int excl = running + warpbase + x - v;
        if (idx < n) {
            g_ofs[rel][idx] = excl;
            g_cur[rel][idx] = excl;
        }
        int total = shw[31];
        __syncthreads();
        running += total;
    }
    if (t == 0) g_ofs[rel][n] = running;
}

// ---------------- permute src ids into CSR order ---------------------------------
__global__ void permute_kernel(const int* __restrict__ ei0, const int* __restrict__ ei1,
                               const int* __restrict__ ei2, int E) {
    int rel = blockIdx.y;
    const int* ei = (rel == 0) ? ei0 : (rel == 1) ? ei1 : ei2;
    int e = blockIdx.x * blockDim.x + threadIdx.x;
    if (e < E) {
        int src = __ldg(ei + e);
        int dst = __ldg(ei + E + e);
        int pos = atomicAdd(&g_cur[rel][dst], 1);
        g_esrc[rel * MAX_E + pos] = src;
    }
}

// ---------------- fused aggregation + x-feature split ----------------------------
// gridDim.y: 0..2 = CSR mean aggregation -> bf16 hi/lo; 3,4 = split x_user/x_item
__global__ void aggregate_kernel(const float* __restrict__ x_user,
                                 const float* __restrict__ x_item,
                                 int n_user, int n_item) {
    int rel = blockIdx.y;

    if (rel >= 3) {
        // x feature pre-split: one float4 per thread
        int which = rel - 3;
        const float* x = which ? x_item : x_user;
        __nv_bfloat16* hi = which ? g_hi_xi : g_hi_xu;
        __nv_bfloat16* lo = which ? g_lo_xi : g_lo_xu;
        int n4 = (which ? n_item : n_user) * 32;
        int t = blockIdx.x * blockDim.x + threadIdx.x;
        if (t < n4) {
            float4 v = __ldg((const float4*)x + t);
            uint32_t h0, l0, h1, l1;
            f2_to_hilo(v.x, v.y, h0, l0);
            f2_to_hilo(v.z, v.w, h1, l1);
            *(uint2*)(hi + (size_t)t * 4) = make_uint2(h0, h1);
            *(uint2*)(lo + (size_t)t * 4) = make_uint2(l0, l1);
        }
        return;
    }

    int n = (rel == 0) ? n_item : n_user;
    const float* x = (rel == 1) ? x_item : x_user;
    __nv_bfloat16* mhi = (rel == 0) ? g_hi_rates : (rel == 1) ? g_hi_rev : g_hi_fol;
    __nv_bfloat16* mlo = (rel == 0) ? g_lo_rates : (rel == 1) ? g_lo_rev : g_lo_fol;

    int w = (blockIdx.x * blockDim.x + threadIdx.x) >> 5;
    int lane = threadIdx.x & 31;
    if (w >= n) return;

    int start = g_ofs[rel][w];
    int end   = g_ofs[rel][w + 1];
    const int* esrc = g_esrc + rel * MAX_E;
    const size_t loff = (size_t)(lane * 4);

    float4 a0 = make_float4(0.f, 0.f, 0.f, 0.f);
    float4 a1 = make_float4(0.f, 0.f, 0.f, 0.f);
    float4 a2 = make_float4(0.f, 0.f, 0.f, 0.f);
    float4 a3 = make_float4(0.f, 0.f, 0.f, 0.f);
    int e = start;
    for (; e + 4 <= end; e += 4) {
        int s0 = __ldg(esrc + e);
        int s1 = __ldg(esrc + e + 1);
        int s2 = __ldg(esrc + e + 2);
        int s3 = __ldg(esrc + e + 3);
        float4 v0 = *(const float4*)(x + (size_t)s0 * D + loff);
        float4 v1 = *(const float4*)(x + (size_t)s1 * D + loff);
        float4 v2 = *(const float4*)(x + (size_t)s2 * D + loff);
        float4 v3 = *(const float4*)(x + (size_t)s3 * D + loff);
        a0.x += v0.x; a0.y += v0.y; a0.z += v0.z; a0.w += v0.w;
        a1.x += v1.x; a1.y += v1.y; a1.z += v1.z; a1.w += v1.w;
        a2.x += v2.x; a2.y += v2.y; a2.z += v2.z; a2.w += v2.w;
        a3.x += v3.x; a3.y += v3.y; a3.z += v3.z; a3.w += v3.w;
    }
    for (; e < end; e++) {
        int s0 = __ldg(esrc + e);
        float4 v0 = *(const float4*)(x + (size_t)s0 * D + loff);
        a0.x += v0.x; a0.y += v0.y; a0.z += v0.z; a0.w += v0.w;
    }
    int deg = end - start;
    float sc = (deg > 0) ? (1.0f / (float)deg) : 0.0f;
    float4 r;
    r.x = (a0.x + a1.x + a2.x + a3.x) * sc;
    r.y = (a0.y + a1.y + a2.y + a3.y) * sc;
    r.z = (a0.z + a1.z + a2.z + a3.z) * sc;
    r.w = (a0.w + a1.w + a2.w + a3.w) * sc;
    uint32_t h0, l0, h1, l1;
    f2_to_hilo(r.x, r.y, h0, l0);
    f2_to_hilo(r.z, r.w, h1, l1);
    *(uint2*)(mhi + (size_t)w * D + loff) = make_uint2(h0, h1);
    *(uint2*)(mlo + (size_t)w * D + loff) = make_uint2(l0, l1);
}

// ---------------- combined-weight prep: transposed bf16 hi/lo --------------------
__global__ void build_user_wc(const float* __restrict__ Wl_rev, const float* __restrict__ bl_rev,
                              const float* __restrict__ Wr_rev,
                              const float* __restrict__ Wl_fol, const float* __restrict__ bl_fol,
                              const float* __restrict__ Wr_fol) {
    int t = blockIdx.x * blockDim.x + threadIdx.x;
    if (t < 384 * 128) {
        int k = t >> 7, j = t & 127;
        float v;
        if (k < 128)       v = 0.5f * Wl_rev[j * D + k];
        else if (k < 256)  v = 0.5f * Wl_fol[j * D + (k - 128)];
        else               v = 0.5f * (Wr_rev[j * D + (k - 256)] + Wr_fol[j * D + (k - 256)]);
        __nv_bfloat16 hi = __float2bfloat16_rn(v);
        __nv_bfloat16 lo = __float2bfloat16_rn(v - __bfloat162float(hi));
        g_wbt_user_hi[j * 384 + k] = hi;
        g_wbt_user_lo[j * 384 + k] = lo;
    }
    if (t < D) g_bias_user[t] = 0.5f * (bl_rev[t] + bl_fol[t]);
}

__global__ void build_item_wc(const float* __restrict__ Wl, const float* __restrict__ bl,
                              const float* __restrict__ Wr) {
    int t = blockIdx.x * blockDim.x + threadIdx.x;
    if (t < 256 * 128) {
        int k = t >> 7, j = t & 127;
        float v = (k < 128) ? Wl[j * D + k] : Wr[j * D + (k - 128)];
        __nv_bfloat16 hi = __float2bfloat16_rn(v);
        __nv_bfloat16 lo = __float2bfloat16_rn(v - __bfloat162float(hi));
        g_wbt_item_hi[j * 256 + k] = hi;
        g_wbt_item_lo[j * 256 + k] = lo;
    }
    if (t < D) g_bias_item[t] = bl[t];
}

// ---------------- mma.sync bf16x3 GEMM, single-stage cp.async, occ 2 -------------
// 128x128 output tile per CTA, 256 thr = 8 warps (4 row-groups x 2 col-groups).
// K in chunks of 64; A/B bf16 hi/lo pre-split in global, staged via cp.async.
#define LDB 144
#define SA_HI 0
#define SA_LO 18432
#define SB_HI 36864
#define SB_LO 55296
#define SM_BIAS_OFF 73728
#define SM_TOT (73728 + 512)

__global__ __launch_bounds__(256, 2)
void gemm_mma(float* __restrict__ out_user, float* __restrict__ out_item,
              int n_user, int n_item) {
    extern __shared__ char smem[];
    uint32_t sb = smem_u32(smem);
    const int tid = threadIdx.x;
    const int lane = tid & 31;
    const int w = tid >> 5;
    const int wr = w & 3;          // row group: 32 rows
    const int wc = w >> 2;         // col group: 64 cols
    const int mode = blockIdx.y;   // 0 user, 1 item
    const int nrows = mode ? n_item : n_user;
    const int nch = mode ? 4 : 6;
    const int KS = mode ? 256 : 384;
    const __nv_bfloat16* wbh = mode ? g_wbt_item_hi : g_wbt_user_hi;
    const __nv_bfloat16* wbl = mode ? g_wbt_item_lo : g_wbt_user_lo;
    const float* bias = mode ? g_bias_item : g_bias_user;
    float* out = mode ? out_item : out_user;
    const int row0 = blockIdx.x * 128;
    if (row0 >= nrows) return;

    if (tid < 128) ((float*)(smem + SM_BIAS_OFF))[tid] = bias[tid];

    const int r_st = tid >> 1;     // staging row 0..127
    const int half = tid & 1;      // 32-element half
    const int gra = min(row0 + r_st, nrows - 1);            // clamped source row
    const uint32_t asz = (row0 + r_st < nrows) ? 16u : 0u;  // zero-fill OOB rows

    float acc[2][8][4];
#pragma unroll
    for (int i = 0; i < 2; i++)
#pragma unroll
        for (int j = 0; j < 8; j++)
#pragma unroll
            for (int q = 0; q < 4; q++) acc[i][j][q] = 0.f;

    for (int c = 0; c < nch; c++) {
        const __nv_bfloat16 *ahi, *alo;
        if (mode == 0) {
            if (c < 2)      { ahi = g_hi_rev;   alo = g_lo_rev; }
            else if (c < 4) { ahi = g_hi_fol;   alo = g_lo_fol; }
            else            { ahi = g_hi_xu;    alo = g_lo_xu; }
        } else {
            if (c < 2)      { ahi = g_hi_rates; alo = g_lo_rates; }
            else            { ahi = g_hi_xi;    alo = g_lo_xi; }
        }

        __syncthreads();               // all warps done reading the stage buffer
        {
            uint32_t doff = (uint32_t)(r_st * LDB + half * 64);
            const __nv_bfloat16* sa_h = ahi + (size_t)gra * D + (c & 1) * 64 + half * 32;
            const __nv_bfloat16* sa_l = alo + (size_t)gra * D + (c & 1) * 64 + half * 32;
            const __nv_bfloat16* sb_h = wbh + (size_t)r_st * KS + c * 64 + half * 32;
            const __nv_bfloat16* sb_l = wbl + (size_t)r_st * KS + c * 64 + half * 32;
#pragma unroll
            for (int q = 0; q < 4; q++) {
                CPA16(sb + SA_HI + doff + q * 16, sa_h + q * 8, asz);
                CPA16(sb + SA_LO + doff + q * 16, sa_l + q * 8, asz);
                CPA16(sb + SB_HI + doff + q * 16, sb_h + q * 8, 16u);
                CPA16(sb + SB_LO + doff + q * 16, sb_l + q * 8, 16u);
            }
            CPA_COMMIT();
            CPA_WAIT(0);
        }
        __syncthreads();               // staged data visible to all warps

#pragma unroll
        for (int ks = 0; ks < 4; ks++) {
            uint32_t cb = (uint32_t)(ks * 32 + (lane >> 4) * 16);
            uint32_t ar = (uint32_t)((wr * 32 + (lane & 15)) * LDB);
            uint32_t ah[2][4], al[2][4];
            LDM_X4(ah[0][0], ah[0][1], ah[0][2], ah[0][3], sb + SA_HI + ar + cb);
            LDM_X4(ah[1][0], ah[1][1], ah[1][2], ah[1][3], sb + SA_HI + ar + 16 * LDB + cb);
            LDM_X4(al[0][0], al[0][1], al[0][2], al[0][3], sb + SA_LO + ar + cb);
            LDM_X4(al[1][0], al[1][1], al[1][2], al[1][3], sb + SA_LO + ar + 16 * LDB + cb);
#pragma unroll
            for (int ng = 0; ng < 4; ng++) {
                uint32_t br = (uint32_t)((wc * 64 + ng * 16 + (lane & 15)) * LDB);
                uint32_t bh0, bh1, bh2, bh3, bl0, bl1, bl2, bl3;
                LDM_X4(bh0, bh1, bh2, bh3, sb + SB_HI + br + cb);
                LDM_X4(bl0, bl1, bl2, bl3, sb + SB_LO + br + cb);
#pragma unroll
                for (int mt = 0; mt < 2; mt++) {
                    MMA16816(acc[mt][2 * ng],     ah[mt], bh0, bh2);
                    MMA16816(acc[mt][2 * ng],     al[mt], bh0, bh2);
                    MMA16816(acc[mt][2 * ng],     ah[mt], bl0, bl2);
                    MMA16816(acc[mt][2 * ng + 1], ah[mt], bh1, bh3);
                    MMA16816(acc[mt][2 * ng + 1], al[mt], bh1, bh3);
                    MMA16816(acc[mt][2 * ng + 1], ah[mt], bl1, bl3);
                }
            }
        }
    }

    // ---- epilogue: acc + bias -> out ----
    const float* bs = (const float*)(smem + SM_BIAS_OFF);
#pragma unroll
    for (int mt = 0; mt < 2; mt++) {
        int r0g = row0 + wr * 32 + mt * 16 + (lane >> 2);
        int r1g = r0g + 8;
#pragma unroll
        for (int nt = 0; nt < 8; nt++) {
            int j = wc * 64 + nt * 8 + (lane & 3) * 2;
            float b0 = bs[j], b1 = bs[j + 1];
            if (r0g < nrows) {
                float2 o = make_float2(acc[mt][nt][0] + b0, acc[mt][nt][1] + b1);
                *(float2*)(out + (size_t)r0g * D + j) = o;
            }
            if (r1g < nrows) {
                float2 o = make_float2(acc[mt][nt][2] + b0, acc[mt][nt][3] + b1);
                *(float2*)(out + (size_t)r1g * D + j) = o;
            }
        }
    }
}

// ---------------- launch ---------------------------------------------------------
extern "C" void kernel_launch(void* const* d_in, const int* in_sizes, int n_in,
                              void* d_out, int out_size) {
    const float* x_user   = (const float*)d_in[0];
    const float* x_item   = (const float*)d_in[1];
    const int*   ei_rates = (const int*)d_in[2];
    const int*   ei_rev   = (const int*)d_in[3];
    const int*   ei_fol   = (const int*)d_in[4];
    const float* Wl_rates = (const float*)d_in[5];
    const float* bl_rates = (const float*)d_in[6];
    const float* Wr_rates = (const float*)d_in[7];
    const float* Wl_rev   = (const float*)d_in[8];
    const float* bl_rev   = (const float*)d_in[9];
    const float* Wr_rev   = (const float*)d_in[10];
    const float* Wl_fol   = (const float*)d_in[11];
    const float* bl_fol   = (const float*)d_in[12];
    const float* Wr_fol   = (const float*)d_in[13];

    const int n_user = in_sizes[0] / D;
    const int n_item = in_sizes[1] / D;
    const int E      = in_sizes[2] / 2;

    float* out_user = (float*)d_out;
    float* out_item = out_user + (size_t)n_user * D;

    // opt-in to >48KB dynamic smem (host attribute, not an allocation)
    cudaFuncSetAttribute(gemm_mma, cudaFuncAttributeMaxDynamicSharedMemorySize, SM_TOT);

    // 1) prep: zero counters, split weights to bf16 hi/lo (tiny)
    zero_deg<<<(NPAD + 255) / 256, 256>>>();
    build_user_wc<<<(384 * 128 + 255) / 256, 256>>>(Wl_rev, bl_rev, Wr_rev,
                                                    Wl_fol, bl_fol, Wr_fol);
    build_item_wc<<<(256 * 128 + 255) / 256, 256>>>(Wl_rates, bl_rates, Wr_rates);

    // 2) CSR build: histogram -> scan -> permute
    {
        dim3 grid((E + 255) / 256, 3);
        hist_kernel<<<grid, 256>>>(ei_rates, ei_rev, ei_fol, E);
        scan_kernel<<<3, 1024>>>(n_item, n_user, n_user);
        permute_kernel<<<grid, 256>>>(ei_rates, ei_rev, ei_fol, E);
    }

    // 3) fused: aggregation (3 relations) + x feature split (2), one launch
    {
        int max_n = (n_user > n_item) ? n_user : n_item;
        int gx_agg = (max_n + 7) / 8;
        int gx_cvt = (max_n * 32 + 255) / 256;
        int gx = (gx_agg > gx_cvt) ? gx_agg : gx_cvt;
        dim3 grid(gx, 5);
        aggregate_kernel<<<grid, 256>>>(x_user, x_item, n_user, n_item);
    }

    // 4) mma.sync bf16x3 GEMM + bias, occ-2 single-stage pipeline
    {
        int max_rows = (n_user > n_item) ? n_user : n_item;
        dim3 grid((max_rows + 127) / 128, 2);
        gemm_mma<<<grid, 256, SM_TOT>>>(out_user, out_item, n_user, n_item);
    }
}